// round 2
// baseline (speedup 1.0000x reference)
#include <cuda_runtime.h>
#include <math.h>
#include <limits.h>

#define HDIM 128
#define SDIM 32
#define KTOP 8
#define NB1  1024   // fused stage-1 blocks

// Scratch (__device__ globals; no allocation allowed)
__device__ float g_cand_v[NB1 * KTOP];
__device__ int   g_cand_i[NB1 * KTOP];
__device__ float g_top_v[KTOP];
__device__ int   g_top_i[KTOP];

__device__ __forceinline__ bool better(float va, int ia, float vb, int ib) {
    // jax.lax.top_k ordering: higher value first, ties -> lower index
    return (va > vb) || (va == vb && ia < ib);
}

__device__ __forceinline__ void insert_topk(float* lv, int* li, float v, int c) {
    if (better(v, c, lv[KTOP - 1], li[KTOP - 1])) {
        int j = KTOP - 1;
#pragma unroll
        for (; j > 0; --j) {
            if (better(v, c, lv[j - 1], li[j - 1])) {
                lv[j] = lv[j - 1];
                li[j] = li[j - 1];
            } else break;
        }
        lv[j] = v;
        li[j] = c;
    }
}

// ---------------------------------------------------------------------------
// Kernel 1 (fused): cosine sims of query row 0 vs all embeddings + per-block
// top-8. Warp per embedding, grid-stride over groups of 4 embeddings (MLP=4).
// Every lane maintains an identical top-8 (butterfly shfl gives all lanes the
// reduced sums), avoiding divergence; lane 0 publishes per-warp list.
// ---------------------------------------------------------------------------
__global__ void sims_topk_kernel(const float* __restrict__ q,
                                 const float* __restrict__ emb,
                                 int C) {
    __shared__ float sv[8 * KTOP];
    __shared__ int   si[8 * KTOP];

    const int lane  = threadIdx.x & 31;
    const int wib   = threadIdx.x >> 5;                         // warp in block
    const int warp  = blockIdx.x * (blockDim.x >> 5) + wib;     // global warp
    const int nwarp = gridDim.x * (blockDim.x >> 5);

    // query row 0 slice + its norm (replicated per warp; trivial)
    const float4 q4 = reinterpret_cast<const float4*>(q)[lane];
    float qsq = q4.x * q4.x + q4.y * q4.y + q4.z * q4.z + q4.w * q4.w;
#pragma unroll
    for (int o = 16; o; o >>= 1) qsq += __shfl_xor_sync(0xffffffffu, qsq, o);
    const float rqn = 1.0f / fmaxf(sqrtf(qsq), 1e-8f);

    float lv[KTOP];
    int   li[KTOP];
#pragma unroll
    for (int j = 0; j < KTOP; ++j) { lv[j] = -INFINITY; li[j] = INT_MAX; }

    const int ngroups = (C + 3) >> 2;
    for (int g = warp; g < ngroups; g += nwarp) {
        const int c0 = g * 4;
        float dot[4], esq[4];
#pragma unroll
        for (int j = 0; j < 4; ++j) {
            const int c = c0 + j;
            if (c < C) {
                const float4 e4 =
                    reinterpret_cast<const float4*>(emb + (size_t)c * HDIM)[lane];
                dot[j] = q4.x * e4.x + q4.y * e4.y + q4.z * e4.z + q4.w * e4.w;
                esq[j] = e4.x * e4.x + e4.y * e4.y + e4.z * e4.z + e4.w * e4.w;
            } else {
                dot[j] = 0.0f; esq[j] = 1.0f;
            }
        }
#pragma unroll
        for (int o = 16; o; o >>= 1) {
#pragma unroll
            for (int j = 0; j < 4; ++j) {
                dot[j] += __shfl_xor_sync(0xffffffffu, dot[j], o);
                esq[j] += __shfl_xor_sync(0xffffffffu, esq[j], o);
            }
        }
#pragma unroll
        for (int j = 0; j < 4; ++j) {
            const int c = c0 + j;
            if (c < C) {
                const float sim = dot[j] * rqn / fmaxf(sqrtf(esq[j]), 1e-8f);
                insert_topk(lv, li, sim, c);
            }
        }
    }

    // publish per-warp lists
    if (lane < KTOP) {
        sv[wib * KTOP + lane] = lv[lane];
        si[wib * KTOP + lane] = li[lane];
    }
    __syncthreads();

    // thread 0: 8-way merge of 8 sorted lists -> block top-8
    if (threadIdx.x == 0) {
        int head[8] = {0, 0, 0, 0, 0, 0, 0, 0};
        const int nw = blockDim.x >> 5;   // 8
#pragma unroll
        for (int o = 0; o < KTOP; ++o) {
            int bw = -1; float bv = -INFINITY; int bi = INT_MAX;
            for (int w = 0; w < nw; ++w) {
                if (head[w] < KTOP) {
                    const float v = sv[w * KTOP + head[w]];
                    const int   i = si[w * KTOP + head[w]];
                    if (bw < 0 || better(v, i, bv, bi)) { bw = w; bv = v; bi = i; }
                }
            }
            head[bw]++;
            g_cand_v[blockIdx.x * KTOP + o] = bv;
            g_cand_i[blockIdx.x * KTOP + o] = bi;
        }
    }
}

// ---------------------------------------------------------------------------
// Kernel 2: merge NB1*KTOP = 8192 candidates -> global top-8, write scores.
// ---------------------------------------------------------------------------
__global__ void topk_final(float* __restrict__ out) {
    __shared__ float sv[256 * KTOP];
    __shared__ int   si[256 * KTOP];
    const int t = threadIdx.x;

    float lv[KTOP];
    int   li[KTOP];
#pragma unroll
    for (int j = 0; j < KTOP; ++j) { lv[j] = -INFINITY; li[j] = INT_MAX; }

    for (int c = t; c < NB1 * KTOP; c += 256)
        insert_topk(lv, li, g_cand_v[c], g_cand_i[c]);

#pragma unroll
    for (int j = 0; j < KTOP; ++j) { sv[t * KTOP + j] = lv[j]; si[t * KTOP + j] = li[j]; }
    __syncthreads();

    for (int s = 128; s > 0; s >>= 1) {
        if (t < s) {
            float mv[KTOP]; int mi[KTOP];
            int a = 0, b = 0;
#pragma unroll
            for (int j = 0; j < KTOP; ++j) {
                const float va = sv[t * KTOP + a];       const int ia = si[t * KTOP + a];
                const float vb = sv[(t + s) * KTOP + b]; const int ib = si[(t + s) * KTOP + b];
                if (better(va, ia, vb, ib)) { mv[j] = va; mi[j] = ia; ++a; }
                else                        { mv[j] = vb; mi[j] = ib; ++b; }
            }
#pragma unroll
            for (int j = 0; j < KTOP; ++j) { sv[t * KTOP + j] = mv[j]; si[t * KTOP + j] = mi[j]; }
        }
        __syncthreads();
    }

    if (t < KTOP) {
        g_top_v[t] = sv[t];
        g_top_i[t] = si[t];
        out[KTOP * SDIM * HDIM + t] = sv[t];   // top_scores[0]
    }
}

// ---------------------------------------------------------------------------
// Kernel 3: gather 8 episodes [8,32,128]; 8 blocks per episode for parallelism.
// ---------------------------------------------------------------------------
__global__ void gather_kernel(const float* __restrict__ episodes,
                              float* __restrict__ out) {
    const int e    = blockIdx.x >> 3;         // 0..7
    const int part = blockIdx.x & 7;          // 0..7
    const int idx  = g_top_i[e];

    const int n4     = SDIM * HDIM / 4;       // 1024 float4 per episode
    const int per    = n4 / 8;                // 128 per block
    const float4* __restrict__ src =
        reinterpret_cast<const float4*>(episodes + (size_t)idx * (SDIM * HDIM)) + part * per;
    float4* __restrict__ dst =
        reinterpret_cast<float4*>(out + (size_t)e * (SDIM * HDIM)) + part * per;

    if (threadIdx.x < per) dst[threadIdx.x] = src[threadIdx.x];
}

extern "C" void kernel_launch(void* const* d_in, const int* in_sizes, int n_in,
                              void* d_out, int out_size) {
    const float* query    = (const float*)d_in[0];  // [B, 128]
    const float* episodes = (const float*)d_in[1];  // [C, 32, 128]
    const float* emb      = (const float*)d_in[2];  // [C, 128]
    (void)n_in; (void)out_size;

    const int C = in_sizes[2] / HDIM;               // 100000

    sims_topk_kernel<<<NB1, 256>>>(query, emb, C);
    topk_final<<<1, 256>>>((float*)d_out);
    gather_kernel<<<64, 128>>>(episodes, (float*)d_out);
}

// round 3
// speedup vs baseline: 2.5913x; 2.5913x over previous
#include <cuda_runtime.h>
#include <math.h>
#include <limits.h>

#define HDIM 128
#define SDIM 32
#define KTOP 8
#define NB1  128      // stage-1 top-k blocks

// Scratch (__device__ globals; no allocation allowed)
__device__ float g_sims[100096];          // padded past C
__device__ float g_cand_v[NB1 * KTOP];
__device__ int   g_cand_i[NB1 * KTOP];
__device__ float g_top_v[KTOP];
__device__ int   g_top_i[KTOP];

__device__ __forceinline__ bool better(float va, int ia, float vb, int ib) {
    // jax.lax.top_k ordering: higher value first, ties -> lower index
    return (va > vb) || (va == vb && ia < ib);
}

__device__ __forceinline__ void insert_topk(float* lv, int* li, float v, int c) {
    if (better(v, c, lv[KTOP - 1], li[KTOP - 1])) {
        int j = KTOP - 1;
#pragma unroll
        for (; j > 0; --j) {
            if (better(v, c, lv[j - 1], li[j - 1])) {
                lv[j] = lv[j - 1];
                li[j] = li[j - 1];
            } else break;
        }
        lv[j] = v;
        li[j] = c;
    }
}

// Shared-memory merge tree: 256 sorted top-8 lists -> slot 0 holds block top-8.
__device__ __forceinline__ void block_merge_topk(float* sv, int* si) {
    const int t = threadIdx.x;
    for (int s = 128; s > 0; s >>= 1) {
        if (t < s) {
            float mv[KTOP]; int mi[KTOP];
            int a = 0, b = 0;
#pragma unroll
            for (int j = 0; j < KTOP; ++j) {
                const float va = sv[t * KTOP + a];       const int ia = si[t * KTOP + a];
                const float vb = sv[(t + s) * KTOP + b]; const int ib = si[(t + s) * KTOP + b];
                if (better(va, ia, vb, ib)) { mv[j] = va; mi[j] = ia; ++a; }
                else                        { mv[j] = vb; mi[j] = ib; ++b; }
            }
#pragma unroll
            for (int j = 0; j < KTOP; ++j) { sv[t * KTOP + j] = mv[j]; si[t * KTOP + j] = mi[j]; }
        }
        __syncthreads();
    }
}

// ---------------------------------------------------------------------------
// Kernel 1: cosine sims, 2 lanes per embedding.
// Lane pair (2k, 2k+1) reads 32B-contiguous halves of a row; q comes from
// shared memory (warp-broadcast LDS); exactly 2 shfls finish dot and ||e||^2.
// ~10 warp-instructions per 512B row -> DRAM-bound.
// ---------------------------------------------------------------------------
__global__ void sims_kernel(const float* __restrict__ q,
                            const float* __restrict__ emb,
                            int C) {
    __shared__ float sq[HDIM];
    __shared__ float s_rqn;
    const int t = threadIdx.x;

    if (t < HDIM) sq[t] = q[t];               // query row 0
    __syncthreads();
    if (t < 32) {
        const float4 a = reinterpret_cast<const float4*>(sq)[t];
        float s = a.x * a.x + a.y * a.y + a.z * a.z + a.w * a.w;
#pragma unroll
        for (int o = 16; o; o >>= 1) s += __shfl_xor_sync(0xffffffffu, s, o);
        if (t == 0) s_rqn = 1.0f / fmaxf(sqrtf(s), 1e-8f);
    }
    __syncthreads();
    const float rqn = s_rqn;

    const int gid  = blockIdx.x * blockDim.x + t;
    const int c    = gid >> 1;                // embedding index
    const int half = gid & 1;                 // which half of the row
    const int cs   = (c < C) ? c : (C - 1);   // clamp; guard only the store

    const float4* __restrict__ row = reinterpret_cast<const float4*>(emb + (size_t)cs * HDIM);
    const float4* __restrict__ qv  = reinterpret_cast<const float4*>(sq);

    float d0 = 0.f, d1 = 0.f, e0 = 0.f, e1 = 0.f;
#pragma unroll 4
    for (int i = 0; i < 16; ++i) {
        const int idx = half + 2 * i;
        const float4 ev = row[idx];
        const float4 qq = qv[idx];
        d0 += ev.x * qq.x + ev.y * qq.y;
        d1 += ev.z * qq.z + ev.w * qq.w;
        e0 += ev.x * ev.x + ev.y * ev.y;
        e1 += ev.z * ev.z + ev.w * ev.w;
    }
    float dot = d0 + d1;
    float esq = e0 + e1;
    dot += __shfl_xor_sync(0xffffffffu, dot, 1);
    esq += __shfl_xor_sync(0xffffffffu, esq, 1);

    if (half == 0 && c < C)
        g_sims[c] = dot * rqn / fmaxf(sqrtf(esq), 1e-8f);
}

// ---------------------------------------------------------------------------
// Kernel 2: stage-1 top-8. 128 blocks grid-stride over g_sims (~3 vals/thread),
// per-thread sorted list, then smem merge tree.
// ---------------------------------------------------------------------------
__global__ void topk_stage1(int C) {
    __shared__ float sv[256 * KTOP];
    __shared__ int   si[256 * KTOP];
    const int t = threadIdx.x;

    float lv[KTOP]; int li[KTOP];
#pragma unroll
    for (int j = 0; j < KTOP; ++j) { lv[j] = -INFINITY; li[j] = INT_MAX; }

    for (int c = blockIdx.x * blockDim.x + t; c < C; c += gridDim.x * blockDim.x)
        insert_topk(lv, li, g_sims[c], c);

#pragma unroll
    for (int j = 0; j < KTOP; ++j) { sv[t * KTOP + j] = lv[j]; si[t * KTOP + j] = li[j]; }
    __syncthreads();
    block_merge_topk(sv, si);

    if (t < KTOP) {
        g_cand_v[blockIdx.x * KTOP + t] = sv[t];
        g_cand_i[blockIdx.x * KTOP + t] = si[t];
    }
}

// ---------------------------------------------------------------------------
// Kernel 3: merge 1024 candidates -> global top-8; write scores into out.
// ---------------------------------------------------------------------------
__global__ void topk_final(float* __restrict__ out) {
    __shared__ float sv[256 * KTOP];
    __shared__ int   si[256 * KTOP];
    const int t = threadIdx.x;

    float lv[KTOP]; int li[KTOP];
#pragma unroll
    for (int j = 0; j < KTOP; ++j) { lv[j] = -INFINITY; li[j] = INT_MAX; }

    for (int c = t; c < NB1 * KTOP; c += 256)
        insert_topk(lv, li, g_cand_v[c], g_cand_i[c]);

#pragma unroll
    for (int j = 0; j < KTOP; ++j) { sv[t * KTOP + j] = lv[j]; si[t * KTOP + j] = li[j]; }
    __syncthreads();
    block_merge_topk(sv, si);

    if (t < KTOP) {
        g_top_v[t] = sv[t];
        g_top_i[t] = si[t];
        out[KTOP * SDIM * HDIM + t] = sv[t];   // top_scores[0]
    }
}

// ---------------------------------------------------------------------------
// Kernel 4: gather top-8 episodes [8,32,128]; 8 blocks per episode.
// ---------------------------------------------------------------------------
__global__ void gather_kernel(const float* __restrict__ episodes,
                              float* __restrict__ out) {
    const int e    = blockIdx.x >> 3;
    const int part = blockIdx.x & 7;
    const int idx  = g_top_i[e];

    const int per = (SDIM * HDIM / 4) / 8;    // 128 float4 per block
    const float4* __restrict__ src =
        reinterpret_cast<const float4*>(episodes + (size_t)idx * (SDIM * HDIM)) + part * per;
    float4* __restrict__ dst =
        reinterpret_cast<float4*>(out + (size_t)e * (SDIM * HDIM)) + part * per;

    if (threadIdx.x < per) dst[threadIdx.x] = src[threadIdx.x];
}

extern "C" void kernel_launch(void* const* d_in, const int* in_sizes, int n_in,
                              void* d_out, int out_size) {
    const float* query    = (const float*)d_in[0];  // [B, 128]
    const float* episodes = (const float*)d_in[1];  // [C, 32, 128]
    const float* emb      = (const float*)d_in[2];  // [C, 128]
    (void)n_in; (void)out_size;

    const int C = in_sizes[2] / HDIM;               // 100000

    const int blocksA = (2 * C + 255) / 256;        // 2 lanes per embedding
    sims_kernel<<<blocksA, 256>>>(query, emb, C);
    topk_stage1<<<NB1, 256>>>(C);
    topk_final<<<1, 256>>>((float*)d_out);
    gather_kernel<<<64, 128>>>(episodes, (float*)d_out);
}